// round 11
// baseline (speedup 1.0000x reference)
#include <cuda_runtime.h>

// ============================================================================
// SpectralMoEHeads: out[bt, h*64+o] = sum_k S[bt,k] * sum_i x[bt,h*64+i]*W[h,k,i,o]
//   S[bt,k] = phi[bt%2048, k] + sum_i x[bt,i]*diag[k,i]
//
// R9 (tcgen05 unavailable: harness PTX target is compute_103, no '_a' features;
//     legacy mma.sync path, ceiling ~512 MAC/cyc/SM):
//  - R7's cp.async W staging kept (raw f32 -> smem, fed to mma.tf32 truncated).
//  - Mainloop: it-outer / nt-inner with S folded into the A fragment
//    (cvt per it), accumulating DIRECTLY into the 8 persistent MMA chains
//    acc[mt][nt] -> 8 concurrent chains/warp, dependent-MMA gap ~8 issues
//    => HMMA latency fully hidden at 2 CTAs/SM.
// ============================================================================

__device__ float g_scores[8192 * 8];

__device__ __forceinline__ unsigned f2tf32(float f) {
    unsigned u;
    asm("cvt.rna.tf32.f32 %0, %1;" : "=r"(u) : "f"(f));
    return u;
}

__device__ __forceinline__ void mma_tf32_acc(float& c0, float& c1, float& c2, float& c3,
                                             unsigned a0, unsigned a1, unsigned a2, unsigned a3,
                                             unsigned b0, unsigned b1) {
    asm volatile(
        "mma.sync.aligned.m16n8k8.row.col.f32.tf32.tf32.f32 "
        "{%0,%1,%2,%3}, {%4,%5,%6,%7}, {%8,%9}, {%0,%1,%2,%3};\n"
        : "+f"(c0), "+f"(c1), "+f"(c2), "+f"(c3)
        : "r"(a0), "r"(a1), "r"(a2), "r"(a3), "r"(b0), "r"(b1));
}

__device__ __forceinline__ void cp_async16(unsigned dst_smem, const void* src) {
    asm volatile("cp.async.cg.shared.global [%0], [%1], 16;\n"
                 :: "r"(dst_smem), "l"(src) : "memory");
}
__device__ __forceinline__ void cp_commit() {
    asm volatile("cp.async.commit_group;\n" ::: "memory");
}
template <int N>
__device__ __forceinline__ void cp_wait() {
    asm volatile("cp.async.wait_group %0;\n" :: "n"(N) : "memory");
}

// ---------------------------------------------------------------------------
// Scores kernel (unchanged; ~6.5us, near its DRAM floor)
// ---------------------------------------------------------------------------
__global__ __launch_bounds__(256) void scores_kernel(
    const float* __restrict__ x, const float* __restrict__ diag,
    const float* __restrict__ phi)
{
    __shared__ float4 diag_s[8 * 256];

    const int tid = threadIdx.x;
    for (int i = tid; i < 2048; i += 256) diag_s[i] = ((const float4*)diag)[i];
    __syncthreads();

    const int lane = tid & 31;
    const int w    = tid >> 5;
    const int t0   = (blockIdx.x * 8 + w) * 4;

    float acc[4][8];
#pragma unroll
    for (int t = 0; t < 4; ++t)
#pragma unroll
        for (int k = 0; k < 8; ++k) acc[t][k] = 0.f;

#pragma unroll
    for (int c = 0; c < 8; ++c) {
        float4 dv[8];
#pragma unroll
        for (int k = 0; k < 8; ++k) dv[k] = diag_s[k * 256 + c * 32 + lane];
#pragma unroll
        for (int t = 0; t < 4; ++t) {
            float4 xv = ((const float4*)x)[(size_t)(t0 + t) * 256 + c * 32 + lane];
#pragma unroll
            for (int k = 0; k < 8; ++k) {
                acc[t][k] = fmaf(xv.x, dv[k].x, acc[t][k]);
                acc[t][k] = fmaf(xv.y, dv[k].y, acc[t][k]);
                acc[t][k] = fmaf(xv.z, dv[k].z, acc[t][k]);
                acc[t][k] = fmaf(xv.w, dv[k].w, acc[t][k]);
            }
        }
    }

#pragma unroll
    for (int t = 0; t < 4; ++t)
#pragma unroll
        for (int k = 0; k < 8; ++k) {
            float v = acc[t][k];
            v += __shfl_xor_sync(0xffffffffu, v, 16);
            v += __shfl_xor_sync(0xffffffffu, v, 8);
            v += __shfl_xor_sync(0xffffffffu, v, 4);
            v += __shfl_xor_sync(0xffffffffu, v, 2);
            v += __shfl_xor_sync(0xffffffffu, v, 1);
            acc[t][k] = v;
        }

    if (lane == 0) {
#pragma unroll
        for (int t = 0; t < 4; ++t) {
            const int bt = t0 + t;
            float4 p0 = ((const float4*)phi)[(bt & 2047) * 2];
            float4 p1 = ((const float4*)phi)[(bt & 2047) * 2 + 1];
            float4 r0 = make_float4(acc[t][0] + p0.x, acc[t][1] + p0.y,
                                    acc[t][2] + p0.z, acc[t][3] + p0.w);
            float4 r1 = make_float4(acc[t][4] + p1.x, acc[t][5] + p1.y,
                                    acc[t][6] + p1.z, acc[t][7] + p1.w);
            ((float4*)g_scores)[bt * 2]     = r0;
            ((float4*)g_scores)[bt * 2 + 1] = r1;
        }
    }
}

// ---------------------------------------------------------------------------
// Main kernel: CTA = (token tile 128, head). 256 threads = 8 warps,
// warp grid 4(m) x 2(n), warp tile 32x32, mma m16n8k8 tf32.
// smem: x_s [128][68] f32, Wraw [2][64][72] raw f32 (cp.async), S_s [128][9].
// ---------------------------------------------------------------------------
#define XS_STRIDE 68
#define WS_STRIDE 72
#define WS_BUF    (64 * WS_STRIDE)          // 4608 floats per buffer
#define SS_STRIDE 9
#define MAIN_SMEM_FLOATS (128 * XS_STRIDE + 2 * WS_BUF + 128 * SS_STRIDE)

__global__ __launch_bounds__(256, 2) void spectral_main_kernel(
    const float* __restrict__ x, const float* __restrict__ w,
    float* __restrict__ out)
{
    extern __shared__ float sm[];
    float* x_s  = sm;                            // 128 * 68
    float* Wraw = sm + 128 * XS_STRIDE;          // 2 * 4608
    float* S_s  = sm + 128 * XS_STRIDE + 2 * WS_BUF;

    const int tid  = threadIdx.x;
    const int h    = blockIdx.y;
    const int bt0  = blockIdx.x * 128;

    const int lane = tid & 31;
    const int wid  = tid >> 5;
    const int gid  = lane >> 2;   // 0..7
    const int tig  = lane & 3;    // 0..3
    const int wm   = wid & 3;     // m warp coord (x32)
    const int wn   = wid >> 2;    // n warp coord (x32)

    const float* Wh = w + (size_t)h * 8 * 64 * 64;   // W[h] : [512][64] row-major

    const unsigned wraw_smem = (unsigned)__cvta_generic_to_shared(Wraw);
    const int wr_r  = tid >> 4;       // 0..15
    const int wr_c4 = tid & 15;       // float4 column

    // ---- issue cp.async for W chunks 0 and 1 ----
#pragma unroll
    for (int c = 0; c < 2; ++c) {
        const float* src = Wh + (size_t)c * 4096;
        unsigned dbase = wraw_smem + c * (WS_BUF * 4);
#pragma unroll
        for (int j = 0; j < 4; ++j) {
            int r = wr_r + j * 16;
            cp_async16(dbase + (r * WS_STRIDE + wr_c4 * 4) * 4,
                       src + r * 64 + wr_c4 * 4);
        }
        cp_commit();
    }

    // ---- stage x tile (128 rows x 64 cols) ----
#pragma unroll
    for (int j = 0; j < 8; ++j) {
        int idx = tid + j * 256;
        int r = idx >> 4, c4 = idx & 15;
        float4 v = ((const float4*)x)[(size_t)(bt0 + r) * 256 + h * 16 + c4];
        float* d = x_s + r * XS_STRIDE + c4 * 4;
        d[0] = v.x; d[1] = v.y; d[2] = v.z; d[3] = v.w;
    }
    // ---- stage scores ----
#pragma unroll
    for (int j = 0; j < 4; ++j) {
        int idx = tid + j * 256;
        int r = idx >> 3, k = idx & 7;
        S_s[r * SS_STRIDE + k] = g_scores[(bt0 + r) * 8 + k];
    }
    __syncthreads();

    // ---- x fragments (raw f32, scaled+converted per k in the mainloop) ----
    float xf[2][8][4];
#pragma unroll
    for (int mt = 0; mt < 2; ++mt) {
        const int t0 = wm * 32 + mt * 16 + gid;
        const int t1 = t0 + 8;
#pragma unroll
        for (int it = 0; it < 8; ++it) {
            const int i0 = it * 8 + tig;
            xf[mt][it][0] = x_s[t0 * XS_STRIDE + i0];
            xf[mt][it][1] = x_s[t1 * XS_STRIDE + i0];
            xf[mt][it][2] = x_s[t0 * XS_STRIDE + i0 + 4];
            xf[mt][it][3] = x_s[t1 * XS_STRIDE + i0 + 4];
        }
    }

    float acc[2][4][4];
#pragma unroll
    for (int mt = 0; mt < 2; ++mt)
#pragma unroll
        for (int nt = 0; nt < 4; ++nt)
#pragma unroll
            for (int r = 0; r < 4; ++r) acc[mt][nt][r] = 0.f;

#pragma unroll 1
    for (int k = 0; k < 8; ++k) {
        if (k < 7) cp_wait<1>(); else cp_wait<0>();
        __syncthreads();   // W chunk k visible to all warps

        const int tb = wm * 32 + gid;
        const float s00 = S_s[(tb)      * SS_STRIDE + k];
        const float s01 = S_s[(tb + 8)  * SS_STRIDE + k];
        const float s10 = S_s[(tb + 16) * SS_STRIDE + k];
        const float s11 = S_s[(tb + 24) * SS_STRIDE + k];

        // raw f32 bits fed to mma.tf32 (HW reads the tf32 field = RZ truncation)
        const unsigned* Wb = (const unsigned*)(Wraw + (k & 1) * WS_BUF);
        const int colbase = tig * WS_STRIDE + wn * 32 + gid;

        // it-outer / nt-inner: 8 persistent chains acc[mt][nt]; the gap
        // between dependent MMAs on one chain is 8 issued MMAs -> latency hidden.
#pragma unroll
        for (int it = 0; it < 8; ++it) {
            unsigned a0[4], a1[4];
            a0[0] = f2tf32(s00 * xf[0][it][0]);
            a0[1] = f2tf32(s01 * xf[0][it][1]);
            a0[2] = f2tf32(s00 * xf[0][it][2]);
            a0[3] = f2tf32(s01 * xf[0][it][3]);
            a1[0] = f2tf32(s10 * xf[1][it][0]);
            a1[1] = f2tf32(s11 * xf[1][it][1]);
            a1[2] = f2tf32(s10 * xf[1][it][2]);
            a1[3] = f2tf32(s11 * xf[1][it][3]);

            const int r0 = colbase + it * (8 * WS_STRIDE);
#pragma unroll
            for (int nt = 0; nt < 4; ++nt) {
                unsigned b0 = Wb[r0 + nt * 8];
                unsigned b1 = Wb[r0 + nt * 8 + 4 * WS_STRIDE];
                mma_tf32_acc(acc[0][nt][0], acc[0][nt][1], acc[0][nt][2], acc[0][nt][3],
                             a0[0], a0[1], a0[2], a0[3], b0, b1);
                mma_tf32_acc(acc[1][nt][0], acc[1][nt][1], acc[1][nt][2], acc[1][nt][3],
                             a1[0], a1[1], a1[2], a1[3], b0, b1);
            }
        }

        __syncthreads();   // all warps done reading buffer (k&1)
        if (k < 6) {
            const float* src = Wh + (size_t)(k + 2) * 4096;
            unsigned dbase = wraw_smem + (k & 1) * (WS_BUF * 4);
#pragma unroll
            for (int j = 0; j < 4; ++j) {
                int r = wr_r + j * 16;
                cp_async16(dbase + (r * WS_STRIDE + wr_c4 * 4) * 4,
                           src + r * 64 + wr_c4 * 4);
            }
            cp_commit();
        }
    }

    // ---- epilogue: fp32 store ----
#pragma unroll
    for (int mt = 0; mt < 2; ++mt) {
        const int t0 = bt0 + wm * 32 + mt * 16 + gid;
#pragma unroll
        for (int nt = 0; nt < 4; ++nt) {
            const int o = h * 64 + wn * 32 + nt * 8 + tig * 2;
            *(float2*)(out + (size_t)t0 * 1024 + o) =
                make_float2(acc[mt][nt][0], acc[mt][nt][1]);
            *(float2*)(out + (size_t)(t0 + 8) * 1024 + o) =
                make_float2(acc[mt][nt][2], acc[mt][nt][3]);
        }
    }
}

// ---------------------------------------------------------------------------
extern "C" void kernel_launch(void* const* d_in, const int* in_sizes, int n_in,
                              void* d_out, int out_size) {
    const float* x    = (const float*)d_in[0];   // [4,2048,1024]
    const float* wgt  = (const float*)d_in[1];   // [16,8,64,64]
    const float* diag = (const float*)d_in[2];   // [8,1024]
    const float* phi  = (const float*)d_in[3];   // [2048,8]
    float* out = (float*)d_out;                  // [4,2048,1024]

    const int main_smem = MAIN_SMEM_FLOATS * 4;
    cudaFuncSetAttribute(spectral_main_kernel,
                         cudaFuncAttributeMaxDynamicSharedMemorySize, main_smem);

    scores_kernel<<<256, 256>>>(x, diag, phi);
    spectral_main_kernel<<<dim3(64, 16), 256, main_smem>>>(x, wgt, out);
}